// round 1
// baseline (speedup 1.0000x reference)
#include <cuda_runtime.h>
#include <math.h>
#include <stdint.h>

// Problem constants
#define NN      1024
#define DF      6
#define TT      60
#define HH      64
#define GG      192      // 3*H
#define RR      64
#define WPAD    68       // padded K-stride for weight rows (bank-conflict mitigation)
#define NEG_VAL (-10000.0f)
#define SLOPE   0.01f

// Inter-kernel scratch (allocation-free rule: __device__ globals)
__device__ float g_h1[NN * HH];
__device__ float g_sa[NN];
__device__ float g_sb[NN];

__device__ __forceinline__ float sigf(float x) { return 1.0f / (1.0f + __expf(-x)); }

// ---------------------------------------------------------------------------
// Kernel 1: fused 2-layer GRU, persistent per-block recurrence.
// grid = 128 blocks * 8 rows, 128 threads/block.
// All recurrent weights in SMEM; h0/h1 in SMEM; per-thread 4x3 register tile.
// ---------------------------------------------------------------------------
#define GRU_THREADS 128
#define GRU_ROWS    8

__global__ void __launch_bounds__(GRU_THREADS, 1)
gru_kernel(const float* __restrict__ x,
           const float* __restrict__ Wih0, const float* __restrict__ Whh0,
           const float* __restrict__ bih0, const float* __restrict__ bhh0,
           const float* __restrict__ Wih1, const float* __restrict__ Whh1,
           const float* __restrict__ bih1, const float* __restrict__ bhh1,
           const float* __restrict__ Wv)
{
    extern __shared__ float smem[];
    float* sWhh0 = smem;                         // 192*68
    float* sWih1 = sWhh0 + GG * WPAD;            // 192*68
    float* sWhh1 = sWih1 + GG * WPAD;            // 192*68
    float* sWih0 = sWhh1 + GG * WPAD;            // 192*8
    float* sB    = sWih0 + GG * 8;               // 4*192 (bih0,bhh0,bih1,bhh1)
    float* sX    = sB + 4 * GG;                  // 8*360
    float* sXt   = sX + GRU_ROWS * 360;          // 2*8*8 (double-buffered x_t)
    float* sH0   = sXt + 2 * GRU_ROWS * 8;       // 8*64
    float* sH1   = sH0 + GRU_ROWS * HH;          // 8*64
    float* sGA   = sH1 + GRU_ROWS * HH;          // 8*192 (x-side gates)
    float* sGB   = sGA + GRU_ROWS * GG;          // 8*192 (h-side gates)

    const int tid = threadIdx.x;
    const int bid = blockIdx.x;
    const int r0  = bid * GRU_ROWS;

    // ---- load weights / biases / x rows into SMEM ----
    for (int i = tid; i < GG * HH; i += GRU_THREADS) {
        int o = i >> 6, k = i & 63;
        sWhh0[o * WPAD + k] = Whh0[i];
        sWih1[o * WPAD + k] = Wih1[i];
        sWhh1[o * WPAD + k] = Whh1[i];
    }
    for (int i = tid; i < GG * DF; i += GRU_THREADS) {
        int o = i / DF, d = i % DF;
        sWih0[o * 8 + d] = Wih0[i];
    }
    for (int i = tid; i < GG; i += GRU_THREADS) {
        sB[i]          = bih0[i];
        sB[GG + i]     = bhh0[i];
        sB[2 * GG + i] = bih1[i];
        sB[3 * GG + i] = bhh1[i];
    }
    for (int i = tid; i < GRU_ROWS * 360; i += GRU_THREADS) {
        int r = i / 360, c = i % 360;
        sX[i] = x[(size_t)(r0 + r) * 360 + c];
    }
    for (int i = tid; i < GRU_ROWS * HH; i += GRU_THREADS) { sH0[i] = 0.f; sH1[i] = 0.f; }
    if (tid < GRU_ROWS * DF) {
        int r = tid / DF, d = tid % DF;
        sXt[r * 8 + d] = sX[r * 360 + d * TT + 0];   // xs[n][t=0][d] = x[n][d*T + t]
    }
    __syncthreads();

    // register tile: 4 rows x 3 outputs per thread (2 row-groups x 64 o-tiles)
    const int rt = tid >> 6;       // 0..1
    const int ot = tid & 63;       // 0..63
    const int o0 = ot * 3;

    for (int t = 0; t < TT; ++t) {
        const int cur = t & 1, nxt = cur ^ 1;

        // ---- Phase A: sGA = x_t @ Wih0^T + bih0 ; sGB = h0 @ Whh0^T + bhh0 ----
        {
            float a[4][3], bb[4][3];
            #pragma unroll
            for (int i = 0; i < 4; i++)
                #pragma unroll
                for (int j = 0; j < 3; j++) { a[i][j] = sB[o0 + j]; bb[i][j] = sB[GG + o0 + j]; }

            #pragma unroll
            for (int d = 0; d < DF; d++) {
                float wv0 = sWih0[(o0 + 0) * 8 + d];
                float wv1 = sWih0[(o0 + 1) * 8 + d];
                float wv2 = sWih0[(o0 + 2) * 8 + d];
                #pragma unroll
                for (int i = 0; i < 4; i++) {
                    float xv = sXt[cur * 64 + (rt * 4 + i) * 8 + d];
                    a[i][0] += xv * wv0; a[i][1] += xv * wv1; a[i][2] += xv * wv2;
                }
            }
            #pragma unroll
            for (int k4 = 0; k4 < 16; k4++) {
                float4 w0 = *(const float4*)&sWhh0[(o0 + 0) * WPAD + k4 * 4];
                float4 w1 = *(const float4*)&sWhh0[(o0 + 1) * WPAD + k4 * 4];
                float4 w2 = *(const float4*)&sWhh0[(o0 + 2) * WPAD + k4 * 4];
                #pragma unroll
                for (int i = 0; i < 4; i++) {
                    float4 h = *(const float4*)&sH0[(rt * 4 + i) * HH + k4 * 4];
                    bb[i][0] += h.x * w0.x + h.y * w0.y + h.z * w0.z + h.w * w0.w;
                    bb[i][1] += h.x * w1.x + h.y * w1.y + h.z * w1.z + h.w * w1.w;
                    bb[i][2] += h.x * w2.x + h.y * w2.y + h.z * w2.z + h.w * w2.w;
                }
            }
            #pragma unroll
            for (int i = 0; i < 4; i++)
                #pragma unroll
                for (int j = 0; j < 3; j++) {
                    sGA[(rt * 4 + i) * GG + o0 + j] = a[i][j];
                    sGB[(rt * 4 + i) * GG + o0 + j] = bb[i][j];
                }
        }
        __syncthreads();

        // ---- Phase B: gate nonlinearity, update h0 ----
        #pragma unroll
        for (int p = 0; p < 4; p++) {
            int item = tid + p * GRU_THREADS;       // 512 items = 8 rows x 64
            int r = item >> 6, c = item & 63;
            float xr = sGA[r * GG + c],      hr = sGB[r * GG + c];
            float xz = sGA[r * GG + 64 + c], hz = sGB[r * GG + 64 + c];
            float xn = sGA[r * GG + 128 + c], hn = sGB[r * GG + 128 + c];
            float rr = sigf(xr + hr);
            float zz = sigf(xz + hz);
            float nn = tanhf(xn + rr * hn);
            float h  = sH0[r * HH + c];
            sH0[r * HH + c] = (1.f - zz) * nn + zz * h;
        }
        if (t + 1 < TT && tid < GRU_ROWS * DF) {
            int r = tid / DF, d = tid % DF;
            sXt[nxt * 64 + r * 8 + d] = sX[r * 360 + d * TT + (t + 1)];
        }
        __syncthreads();

        // ---- Phase C: sGA = h0_new @ Wih1^T + bih1 ; sGB = h1 @ Whh1^T + bhh1 ----
        {
            float a[4][3], bb[4][3];
            #pragma unroll
            for (int i = 0; i < 4; i++)
                #pragma unroll
                for (int j = 0; j < 3; j++) { a[i][j] = sB[2 * GG + o0 + j]; bb[i][j] = sB[3 * GG + o0 + j]; }

            #pragma unroll
            for (int k4 = 0; k4 < 16; k4++) {
                float4 u0 = *(const float4*)&sWih1[(o0 + 0) * WPAD + k4 * 4];
                float4 u1 = *(const float4*)&sWih1[(o0 + 1) * WPAD + k4 * 4];
                float4 u2 = *(const float4*)&sWih1[(o0 + 2) * WPAD + k4 * 4];
                float4 w0 = *(const float4*)&sWhh1[(o0 + 0) * WPAD + k4 * 4];
                float4 w1 = *(const float4*)&sWhh1[(o0 + 1) * WPAD + k4 * 4];
                float4 w2 = *(const float4*)&sWhh1[(o0 + 2) * WPAD + k4 * 4];
                #pragma unroll
                for (int i = 0; i < 4; i++) {
                    float4 g = *(const float4*)&sH0[(rt * 4 + i) * HH + k4 * 4];
                    float4 h = *(const float4*)&sH1[(rt * 4 + i) * HH + k4 * 4];
                    a[i][0]  += g.x * u0.x + g.y * u0.y + g.z * u0.z + g.w * u0.w;
                    a[i][1]  += g.x * u1.x + g.y * u1.y + g.z * u1.z + g.w * u1.w;
                    a[i][2]  += g.x * u2.x + g.y * u2.y + g.z * u2.z + g.w * u2.w;
                    bb[i][0] += h.x * w0.x + h.y * w0.y + h.z * w0.z + h.w * w0.w;
                    bb[i][1] += h.x * w1.x + h.y * w1.y + h.z * w1.z + h.w * w1.w;
                    bb[i][2] += h.x * w2.x + h.y * w2.y + h.z * w2.z + h.w * w2.w;
                }
            }
            #pragma unroll
            for (int i = 0; i < 4; i++)
                #pragma unroll
                for (int j = 0; j < 3; j++) {
                    sGA[(rt * 4 + i) * GG + o0 + j] = a[i][j];
                    sGB[(rt * 4 + i) * GG + o0 + j] = bb[i][j];
                }
        }
        __syncthreads();

        // ---- Phase D: gate nonlinearity, update h1 ----
        #pragma unroll
        for (int p = 0; p < 4; p++) {
            int item = tid + p * GRU_THREADS;
            int r = item >> 6, c = item & 63;
            float xr = sGA[r * GG + c],      hr = sGB[r * GG + c];
            float xz = sGA[r * GG + 64 + c], hz = sGB[r * GG + 64 + c];
            float xn = sGA[r * GG + 128 + c], hn = sGB[r * GG + 128 + c];
            float rr = sigf(xr + hr);
            float zz = sigf(xz + hz);
            float nn = tanhf(xn + rr * hn);
            float h  = sH1[r * HH + c];
            sH1[r * HH + c] = (1.f - zz) * nn + zz * h;
        }
        __syncthreads();
    }

    // ---- epilogue: write final h1, sa = h@Wv[:H], sb = h@Wv[H:2H] ----
    for (int i = tid; i < GRU_ROWS * HH; i += GRU_THREADS)
        g_h1[(size_t)r0 * HH + i] = sH1[i];
    if (tid < GRU_ROWS) {
        float a = 0.f, b2 = 0.f;
        #pragma unroll
        for (int c = 0; c < HH; c++) {
            float h = sH1[tid * HH + c];
            a  += h * Wv[c];
            b2 += h * Wv[HH + c];
        }
        g_sa[r0 + tid] = a;
        g_sb[r0 + tid] = b2;
    }
}

// ---------------------------------------------------------------------------
// Kernel 2: per-row attention. One block per node i.
// Reads relation_matrix[i,:,:] (256KB) once; logits+mask in SMEM; softmax;
// agg = valid @ h (h L2-resident); final FC.
// ---------------------------------------------------------------------------
#define ATT_THREADS 256

__global__ void __launch_bounds__(ATT_THREADS)
att_kernel(const float* __restrict__ rel,
           const float* __restrict__ W,
           const float* __restrict__ bsc,
           const float* __restrict__ fc_w,
           const float* __restrict__ fc_b,
           float* __restrict__ out)
{
    __shared__ float sTemp[NN];
    __shared__ float sMask[NN];
    __shared__ float sWv[RR];
    __shared__ float sRed[64];
    __shared__ float sAgg[4 * HH];
    __shared__ float sBcast[2];

    const int tid = threadIdx.x;
    const int i   = blockIdx.x;

    if (tid < RR) sWv[tid] = W[2 * HH + tid];
    __syncthreads();

    const float sa_i = g_sa[i];
    const float bval = bsc[0];

    // logits + mask
    #pragma unroll
    for (int p = 0; p < 4; p++) {
        int j = tid + p * ATT_THREADS;
        const float4* rp = (const float4*)(rel + ((size_t)i * NN + j) * RR);
        float dot = 0.f, ssum = 0.f;
        #pragma unroll
        for (int q = 0; q < 16; q++) {
            float4 v = rp[q];
            ssum += v.x + v.y + v.z + v.w;
            dot  += v.x * sWv[q * 4] + v.y * sWv[q * 4 + 1]
                  + v.z * sWv[q * 4 + 2] + v.w * sWv[q * 4 + 3];
        }
        float w = sa_i + g_sb[j] + dot + bval;
        w = (w >= 0.f) ? w : SLOPE * w;               // leaky relu
        float m  = (ssum != 0.f) ? 1.f : 0.f;         // mask = (sum_r != 0)
        float tv = m * w;
        if (tv == 0.f) tv = NEG_VAL;                  // temp==0 -> NEG (exact ref semantics)
        sTemp[j] = tv;
        sMask[j] = m;
    }
    __syncthreads();

    // row max
    float mx = -INFINITY;
    #pragma unroll
    for (int p = 0; p < 4; p++) mx = fmaxf(mx, sTemp[tid + p * ATT_THREADS]);
    #pragma unroll
    for (int off = 16; off; off >>= 1) mx = fmaxf(mx, __shfl_xor_sync(0xffffffffu, mx, off));
    if ((tid & 31) == 0) sRed[tid >> 5] = mx;
    __syncthreads();
    if (tid == 0) {
        float m2 = sRed[0];
        for (int w = 1; w < 8; w++) m2 = fmaxf(m2, sRed[w]);
        sBcast[0] = m2;
    }
    __syncthreads();
    mx = sBcast[0];

    // exp / masked numerator; denominator over ALL entries (matches softmax)
    float lsum = 0.f;
    #pragma unroll
    for (int p = 0; p < 4; p++) {
        int j = tid + p * ATT_THREADS;
        float e = __expf(sTemp[j] - mx);
        lsum += e;
        sTemp[j] = e * sMask[j];
    }
    #pragma unroll
    for (int off = 16; off; off >>= 1) lsum += __shfl_xor_sync(0xffffffffu, lsum, off);
    if ((tid & 31) == 0) sRed[tid >> 5] = lsum;
    __syncthreads();
    if (tid == 0) {
        float s2 = 0.f;
        for (int w = 0; w < 8; w++) s2 += sRed[w];
        sBcast[1] = s2;
    }
    __syncthreads();
    const float inv = 1.0f / sBcast[1];

    // agg[c] = sum_j p_j * h[j][c]
    const int c = tid & 63, grp = tid >> 6;
    float acc = 0.f;
    #pragma unroll 4
    for (int j = grp; j < NN; j += 4)
        acc += sTemp[j] * g_h1[(size_t)j * HH + c];
    sAgg[grp * HH + c] = acc;
    __syncthreads();

    if (tid < HH) {
        float agg = (sAgg[tid] + sAgg[HH + tid] + sAgg[2 * HH + tid] + sAgg[3 * HH + tid]) * inv;
        sRed[tid] = g_h1[(size_t)i * HH + tid] * fc_w[tid] + agg * fc_w[HH + tid];
    }
    __syncthreads();
    if (tid == 0) {
        float s = 0.f;
        for (int q = 0; q < HH; q++) s += sRed[q];
        out[i] = s + fc_b[0];
    }
}

// ---------------------------------------------------------------------------
// Launch
// inputs: 0:x 1:relation_matrix 2:W 3:b 4:fc_w 5:fc_b
//         6:Wih0 7:Whh0 8:bih0 9:bhh0 10:Wih1 11:Whh1 12:bih1 13:bhh1
// ---------------------------------------------------------------------------
extern "C" void kernel_launch(void* const* d_in, const int* in_sizes, int n_in,
                              void* d_out, int out_size)
{
    const float* x    = (const float*)d_in[0];
    const float* rel  = (const float*)d_in[1];
    const float* W    = (const float*)d_in[2];
    const float* b    = (const float*)d_in[3];
    const float* fc_w = (const float*)d_in[4];
    const float* fc_b = (const float*)d_in[5];
    const float* Wih0 = (const float*)d_in[6];
    const float* Whh0 = (const float*)d_in[7];
    const float* bih0 = (const float*)d_in[8];
    const float* bhh0 = (const float*)d_in[9];
    const float* Wih1 = (const float*)d_in[10];
    const float* Whh1 = (const float*)d_in[11];
    const float* bih1 = (const float*)d_in[12];
    const float* bhh1 = (const float*)d_in[13];
    float* out = (float*)d_out;

    const size_t gru_smem =
        (3 * GG * WPAD + GG * 8 + 4 * GG + GRU_ROWS * 360 + 2 * GRU_ROWS * 8 +
         2 * GRU_ROWS * HH + 2 * GRU_ROWS * GG) * sizeof(float);
    cudaFuncSetAttribute(gru_kernel, cudaFuncAttributeMaxDynamicSharedMemorySize,
                         (int)gru_smem);

    gru_kernel<<<NN / GRU_ROWS, GRU_THREADS, gru_smem>>>(
        x, Wih0, Whh0, bih0, bhh0, Wih1, Whh1, bih1, bhh1, W);

    att_kernel<<<NN, ATT_THREADS>>>(rel, W, b, fc_w, fc_b, out);
}

// round 2
// speedup vs baseline: 1.6283x; 1.6283x over previous
#include <cuda_runtime.h>
#include <math.h>
#include <stdint.h>

// Problem constants
#define NN      1024
#define DF      6
#define TT      60
#define HH      64
#define GG      192      // 3*H
#define RR      64
#define WPAD    68       // padded K-stride (3*WPAD*4 = 816 B lane stride: conflict-free)
#define NEG_VAL (-10000.0f)
#define SLOPE   0.01f

// Inter-kernel scratch (allocation-free rule: __device__ globals)
__device__ float g_h1[NN * HH];
__device__ float g_sa[NN];
__device__ float g_sb[NN];
__device__ float g_dot[NN * NN];   // 4 MB
__device__ float g_sum[NN * NN];   // 4 MB

typedef unsigned long long u64;

// Packed 2-wide fp32 FMA (Blackwell sm_100+): d = a*b + c elementwise on f32x2
__device__ __forceinline__ u64 ffma2(u64 a, u64 b, u64 c) {
    u64 d;
    asm("fma.rn.f32x2 %0, %1, %2, %3;" : "=l"(d) : "l"(a), "l"(b), "l"(c));
    return d;
}
__device__ __forceinline__ float hsum2(u64 v) {
    float lo, hi;
    asm("mov.b64 {%0,%1}, %2;" : "=f"(lo), "=f"(hi) : "l"(v));
    return lo + hi;
}
__device__ __forceinline__ float tanh_fast(float x) {
    float y;
    asm("tanh.approx.f32 %0, %1;" : "=f"(y) : "f"(x));
    return y;
}
__device__ __forceinline__ float sig_fast(float x) {
    return 0.5f * tanh_fast(0.5f * x) + 0.5f;
}

// ---------------------------------------------------------------------------
// Kernel 1: fused 2-layer GRU, persistent per-block recurrence.
// 128 blocks x 8 rows, 256 threads/block (2 warps/SMSP for latency hiding).
// Per-thread tile: 2 rows x 3 gate-outputs; inner product via fma.rn.f32x2.
// ---------------------------------------------------------------------------
#define GRU_THREADS 256
#define GRU_ROWS    8

__global__ void __launch_bounds__(GRU_THREADS, 1)
gru_kernel(const float* __restrict__ x,
           const float* __restrict__ Wih0, const float* __restrict__ Whh0,
           const float* __restrict__ bih0, const float* __restrict__ bhh0,
           const float* __restrict__ Wih1, const float* __restrict__ Whh1,
           const float* __restrict__ bih1, const float* __restrict__ bhh1,
           const float* __restrict__ Wv)
{
    extern __shared__ float smem[];
    float* sWhh0 = smem;                         // 192*68
    float* sWih1 = sWhh0 + GG * WPAD;            // 192*68
    float* sWhh1 = sWih1 + GG * WPAD;            // 192*68
    float* sWih0 = sWhh1 + GG * WPAD;            // 192*8
    float* sB    = sWih0 + GG * 8;               // 4*192
    float* sX    = sB + 4 * GG;                  // 8*360
    float* sXt   = sX + GRU_ROWS * 360;          // 2*8*8
    float* sH0   = sXt + 2 * GRU_ROWS * 8;       // 8*64
    float* sH1   = sH0 + GRU_ROWS * HH;          // 8*64
    float* sGA   = sH1 + GRU_ROWS * HH;          // 8*192
    float* sGB   = sGA + GRU_ROWS * GG;          // 8*192

    const int tid = threadIdx.x;
    const int r0  = blockIdx.x * GRU_ROWS;

    // ---- load weights / biases / x rows into SMEM ----
    for (int i = tid; i < GG * HH; i += GRU_THREADS) {
        int o = i >> 6, k = i & 63;
        sWhh0[o * WPAD + k] = Whh0[i];
        sWih1[o * WPAD + k] = Wih1[i];
        sWhh1[o * WPAD + k] = Whh1[i];
    }
    for (int i = tid; i < GG * DF; i += GRU_THREADS) {
        int o = i / DF, d = i % DF;
        sWih0[o * 8 + d] = Wih0[i];
    }
    for (int i = tid; i < GG; i += GRU_THREADS) {
        sB[i]          = bih0[i];
        sB[GG + i]     = bhh0[i];
        sB[2 * GG + i] = bih1[i];
        sB[3 * GG + i] = bhh1[i];
    }
    for (int i = tid; i < GRU_ROWS * 360; i += GRU_THREADS) {
        int r = i / 360, c = i % 360;
        sX[i] = x[(size_t)(r0 + r) * 360 + c];
    }
    for (int i = tid; i < GRU_ROWS * HH; i += GRU_THREADS) { sH0[i] = 0.f; sH1[i] = 0.f; }
    if (tid < GRU_ROWS * DF) {
        int r = tid / DF, d = tid % DF;
        sXt[r * 8 + d] = sX[r * 360 + d * TT + 0];
    }
    __syncthreads();

    // tile mapping: 4 row-groups x 64 output-tiles
    const int rt   = tid >> 6;      // 0..3
    const int ot   = tid & 63;      // 0..63
    const int o0   = ot * 3;
    const int row0 = rt * 2;
    const int row1 = rt * 2 + 1;

    for (int t = 0; t < TT; ++t) {
        const int cur = t & 1, nxt = cur ^ 1;

        // ---- Phase A: sGA = x_t @ Wih0^T + bih0 ; sGB = h0 @ Whh0^T + bhh0 ----
        {
            float ax[2][3];
            #pragma unroll
            for (int i = 0; i < 2; i++)
                #pragma unroll
                for (int j = 0; j < 3; j++) ax[i][j] = 0.f;

            #pragma unroll
            for (int d = 0; d < DF; d++) {
                float wv0 = sWih0[(o0 + 0) * 8 + d];
                float wv1 = sWih0[(o0 + 1) * 8 + d];
                float wv2 = sWih0[(o0 + 2) * 8 + d];
                float x0  = sXt[cur * 64 + row0 * 8 + d];
                float x1  = sXt[cur * 64 + row1 * 8 + d];
                ax[0][0] += x0 * wv0; ax[0][1] += x0 * wv1; ax[0][2] += x0 * wv2;
                ax[1][0] += x1 * wv0; ax[1][1] += x1 * wv1; ax[1][2] += x1 * wv2;
            }

            u64 acc[2][3];
            #pragma unroll
            for (int i = 0; i < 2; i++)
                #pragma unroll
                for (int j = 0; j < 3; j++) acc[i][j] = 0ull;

            #pragma unroll
            for (int k4 = 0; k4 < 16; k4++) {
                ulonglong2 w0 = *(const ulonglong2*)&sWhh0[(o0 + 0) * WPAD + k4 * 4];
                ulonglong2 w1 = *(const ulonglong2*)&sWhh0[(o0 + 1) * WPAD + k4 * 4];
                ulonglong2 w2 = *(const ulonglong2*)&sWhh0[(o0 + 2) * WPAD + k4 * 4];
                ulonglong2 h0v = *(const ulonglong2*)&sH0[row0 * HH + k4 * 4];
                ulonglong2 h1v = *(const ulonglong2*)&sH0[row1 * HH + k4 * 4];
                acc[0][0] = ffma2(h0v.x, w0.x, acc[0][0]);
                acc[0][1] = ffma2(h0v.x, w1.x, acc[0][1]);
                acc[0][2] = ffma2(h0v.x, w2.x, acc[0][2]);
                acc[1][0] = ffma2(h1v.x, w0.x, acc[1][0]);
                acc[1][1] = ffma2(h1v.x, w1.x, acc[1][1]);
                acc[1][2] = ffma2(h1v.x, w2.x, acc[1][2]);
                acc[0][0] = ffma2(h0v.y, w0.y, acc[0][0]);
                acc[0][1] = ffma2(h0v.y, w1.y, acc[0][1]);
                acc[0][2] = ffma2(h0v.y, w2.y, acc[0][2]);
                acc[1][0] = ffma2(h1v.y, w0.y, acc[1][0]);
                acc[1][1] = ffma2(h1v.y, w1.y, acc[1][1]);
                acc[1][2] = ffma2(h1v.y, w2.y, acc[1][2]);
            }
            #pragma unroll
            for (int i = 0; i < 2; i++) {
                int rr = (i == 0) ? row0 : row1;
                #pragma unroll
                for (int j = 0; j < 3; j++) {
                    sGA[rr * GG + o0 + j] = sB[o0 + j] + ax[i][j];
                    sGB[rr * GG + o0 + j] = sB[GG + o0 + j] + hsum2(acc[i][j]);
                }
            }
        }
        __syncthreads();

        // ---- Phase B: gate nonlinearity, update h0 ----
        #pragma unroll
        for (int p = 0; p < 2; p++) {
            int item = tid + p * GRU_THREADS;       // 512 items
            int r = item >> 6, c = item & 63;
            float xr = sGA[r * GG + c],       hr = sGB[r * GG + c];
            float xz = sGA[r * GG + 64 + c],  hz = sGB[r * GG + 64 + c];
            float xn = sGA[r * GG + 128 + c], hn = sGB[r * GG + 128 + c];
            float rv = sig_fast(xr + hr);
            float zv = sig_fast(xz + hz);
            float nv = tanh_fast(xn + rv * hn);
            float h  = sH0[r * HH + c];
            sH0[r * HH + c] = (1.f - zv) * nv + zv * h;
        }
        if (t + 1 < TT && tid < GRU_ROWS * DF) {
            int r = tid / DF, d = tid % DF;
            sXt[nxt * 64 + r * 8 + d] = sX[r * 360 + d * TT + (t + 1)];
        }
        __syncthreads();

        // ---- Phase C: sGA = h0_new @ Wih1^T + bih1 ; sGB = h1 @ Whh1^T + bhh1 ----
        {
            u64 a2[2][3], b2[2][3];
            #pragma unroll
            for (int i = 0; i < 2; i++)
                #pragma unroll
                for (int j = 0; j < 3; j++) { a2[i][j] = 0ull; b2[i][j] = 0ull; }

            #pragma unroll
            for (int k4 = 0; k4 < 16; k4++) {
                ulonglong2 u0 = *(const ulonglong2*)&sWih1[(o0 + 0) * WPAD + k4 * 4];
                ulonglong2 u1 = *(const ulonglong2*)&sWih1[(o0 + 1) * WPAD + k4 * 4];
                ulonglong2 u2 = *(const ulonglong2*)&sWih1[(o0 + 2) * WPAD + k4 * 4];
                ulonglong2 w0 = *(const ulonglong2*)&sWhh1[(o0 + 0) * WPAD + k4 * 4];
                ulonglong2 w1 = *(const ulonglong2*)&sWhh1[(o0 + 1) * WPAD + k4 * 4];
                ulonglong2 w2 = *(const ulonglong2*)&sWhh1[(o0 + 2) * WPAD + k4 * 4];
                ulonglong2 g0 = *(const ulonglong2*)&sH0[row0 * HH + k4 * 4];
                ulonglong2 g1 = *(const ulonglong2*)&sH0[row1 * HH + k4 * 4];
                ulonglong2 v0 = *(const ulonglong2*)&sH1[row0 * HH + k4 * 4];
                ulonglong2 v1 = *(const ulonglong2*)&sH1[row1 * HH + k4 * 4];
                a2[0][0] = ffma2(g0.x, u0.x, a2[0][0]);
                a2[0][1] = ffma2(g0.x, u1.x, a2[0][1]);
                a2[0][2] = ffma2(g0.x, u2.x, a2[0][2]);
                a2[1][0] = ffma2(g1.x, u0.x, a2[1][0]);
                a2[1][1] = ffma2(g1.x, u1.x, a2[1][1]);
                a2[1][2] = ffma2(g1.x, u2.x, a2[1][2]);
                b2[0][0] = ffma2(v0.x, w0.x, b2[0][0]);
                b2[0][1] = ffma2(v0.x, w1.x, b2[0][1]);
                b2[0][2] = ffma2(v0.x, w2.x, b2[0][2]);
                b2[1][0] = ffma2(v1.x, w0.x, b2[1][0]);
                b2[1][1] = ffma2(v1.x, w1.x, b2[1][1]);
                b2[1][2] = ffma2(v1.x, w2.x, b2[1][2]);
                a2[0][0] = ffma2(g0.y, u0.y, a2[0][0]);
                a2[0][1] = ffma2(g0.y, u1.y, a2[0][1]);
                a2[0][2] = ffma2(g0.y, u2.y, a2[0][2]);
                a2[1][0] = ffma2(g1.y, u0.y, a2[1][0]);
                a2[1][1] = ffma2(g1.y, u1.y, a2[1][1]);
                a2[1][2] = ffma2(g1.y, u2.y, a2[1][2]);
                b2[0][0] = ffma2(v0.y, w0.y, b2[0][0]);
                b2[0][1] = ffma2(v0.y, w1.y, b2[0][1]);
                b2[0][2] = ffma2(v0.y, w2.y, b2[0][2]);
                b2[1][0] = ffma2(v1.y, w0.y, b2[1][0]);
                b2[1][1] = ffma2(v1.y, w1.y, b2[1][1]);
                b2[1][2] = ffma2(v1.y, w2.y, b2[1][2]);
            }
            #pragma unroll
            for (int i = 0; i < 2; i++) {
                int rr = (i == 0) ? row0 : row1;
                #pragma unroll
                for (int j = 0; j < 3; j++) {
                    sGA[rr * GG + o0 + j] = sB[2 * GG + o0 + j] + hsum2(a2[i][j]);
                    sGB[rr * GG + o0 + j] = sB[3 * GG + o0 + j] + hsum2(b2[i][j]);
                }
            }
        }
        __syncthreads();

        // ---- Phase D: gate nonlinearity, update h1 ----
        #pragma unroll
        for (int p = 0; p < 2; p++) {
            int item = tid + p * GRU_THREADS;
            int r = item >> 6, c = item & 63;
            float xr = sGA[r * GG + c],       hr = sGB[r * GG + c];
            float xz = sGA[r * GG + 64 + c],  hz = sGB[r * GG + 64 + c];
            float xn = sGA[r * GG + 128 + c], hn = sGB[r * GG + 128 + c];
            float rv = sig_fast(xr + hr);
            float zv = sig_fast(xz + hz);
            float nv = tanh_fast(xn + rv * hn);
            float h  = sH1[r * HH + c];
            sH1[r * HH + c] = (1.f - zv) * nv + zv * h;
        }
        __syncthreads();
    }

    // ---- epilogue: write final h1, sa = h@Wv[:H], sb = h@Wv[H:2H] ----
    for (int i = tid; i < GRU_ROWS * HH; i += GRU_THREADS)
        g_h1[(size_t)r0 * HH + i] = sH1[i];
    if (tid < GRU_ROWS) {
        float a = 0.f, b2s = 0.f;
        #pragma unroll
        for (int c = 0; c < HH; c++) {
            float h = sH1[tid * HH + c];
            a   += h * Wv[c];
            b2s += h * Wv[HH + c];
        }
        g_sa[r0 + tid] = a;
        g_sb[r0 + tid] = b2s;
    }
}

// ---------------------------------------------------------------------------
// Kernel 2: streaming rel-dot. 16 lanes per (i,j) pair, butterfly reduce.
// Pure DRAM stream of the 256 MB relation matrix at high MLP.
// ---------------------------------------------------------------------------
#define RD_THREADS 256
#define RD_BLOCKS  2048

__global__ void __launch_bounds__(RD_THREADS)
reldot_kernel(const float* __restrict__ rel, const float* __restrict__ W)
{
    __shared__ float sWv[RR];
    const int tid = threadIdx.x;
    if (tid < RR) sWv[tid] = W[2 * HH + tid];
    __syncthreads();

    const int lane16 = tid & 15;
    const int grp    = tid >> 4;                 // 0..15 pairs per block-iter
    const float4 wv  = *(const float4*)&sWv[lane16 * 4];
    const int stride = RD_BLOCKS * 16;

    for (int p = blockIdx.x * 16 + grp; p < NN * NN; p += stride) {
        float4 v = *(const float4*)&rel[(size_t)p * RR + lane16 * 4];
        float dot  = v.x * wv.x + v.y * wv.y + v.z * wv.z + v.w * wv.w;
        float ssum = v.x + v.y + v.z + v.w;
        #pragma unroll
        for (int off = 8; off; off >>= 1) {
            dot  += __shfl_xor_sync(0xffffffffu, dot,  off);
            ssum += __shfl_xor_sync(0xffffffffu, ssum, off);
        }
        if (lane16 == 0) {
            g_dot[p] = dot;
            g_sum[p] = ssum;
        }
    }
}

// ---------------------------------------------------------------------------
// Kernel 3: per-row softmax + aggregation + FC. One block per node i.
// ---------------------------------------------------------------------------
#define ATT_THREADS 256

__global__ void __launch_bounds__(ATT_THREADS)
att2_kernel(const float* __restrict__ bsc,
            const float* __restrict__ fc_w,
            const float* __restrict__ fc_b,
            float* __restrict__ out)
{
    __shared__ float sTemp[NN];
    __shared__ float sMask[NN];
    __shared__ float sRed[64];
    __shared__ float sAgg[4 * HH];
    __shared__ float sBcast[2];

    const int tid = threadIdx.x;
    const int i   = blockIdx.x;

    const float sa_i = g_sa[i];
    const float bval = bsc[0];

    #pragma unroll
    for (int p = 0; p < 4; p++) {
        int j = tid + p * ATT_THREADS;
        float dot  = g_dot[(size_t)i * NN + j];
        float ssum = g_sum[(size_t)i * NN + j];
        float w = sa_i + g_sb[j] + dot + bval;
        w = (w >= 0.f) ? w : SLOPE * w;
        float m  = (ssum != 0.f) ? 1.f : 0.f;
        float tv = m * w;
        if (tv == 0.f) tv = NEG_VAL;
        sTemp[j] = tv;
        sMask[j] = m;
    }
    __syncthreads();

    // row max
    float mx = -INFINITY;
    #pragma unroll
    for (int p = 0; p < 4; p++) mx = fmaxf(mx, sTemp[tid + p * ATT_THREADS]);
    #pragma unroll
    for (int off = 16; off; off >>= 1) mx = fmaxf(mx, __shfl_xor_sync(0xffffffffu, mx, off));
    if ((tid & 31) == 0) sRed[tid >> 5] = mx;
    __syncthreads();
    if (tid == 0) {
        float m2 = sRed[0];
        for (int w = 1; w < 8; w++) m2 = fmaxf(m2, sRed[w]);
        sBcast[0] = m2;
    }
    __syncthreads();
    mx = sBcast[0];

    // exp; denominator over all entries; masked numerator
    float lsum = 0.f;
    #pragma unroll
    for (int p = 0; p < 4; p++) {
        int j = tid + p * ATT_THREADS;
        float e = __expf(sTemp[j] - mx);
        lsum += e;
        sTemp[j] = e * sMask[j];
    }
    #pragma unroll
    for (int off = 16; off; off >>= 1) lsum += __shfl_xor_sync(0xffffffffu, lsum, off);
    if ((tid & 31) == 0) sRed[tid >> 5] = lsum;
    __syncthreads();
    if (tid == 0) {
        float s2 = 0.f;
        for (int w = 0; w < 8; w++) s2 += sRed[w];
        sBcast[1] = s2;
    }
    __syncthreads();
    const float inv = 1.0f / sBcast[1];

    // agg[c] = sum_j p_j * h[j][c]   (g_h1 is L2-resident: 256 KB)
    const int c = tid & 63, grpq = tid >> 6;
    float acc = 0.f;
    #pragma unroll 4
    for (int j = grpq; j < NN; j += 4)
        acc += sTemp[j] * g_h1[(size_t)j * HH + c];
    sAgg[grpq * HH + c] = acc;
    __syncthreads();

    if (tid < HH) {
        float agg = (sAgg[tid] + sAgg[HH + tid] + sAgg[2 * HH + tid] + sAgg[3 * HH + tid]) * inv;
        sRed[tid] = g_h1[(size_t)i * HH + tid] * fc_w[tid] + agg * fc_w[HH + tid];
    }
    __syncthreads();
    if (tid == 0) {
        float s = 0.f;
        for (int q = 0; q < HH; q++) s += sRed[q];
        out[i] = s + fc_b[0];
    }
}

// ---------------------------------------------------------------------------
// Launch
// inputs: 0:x 1:relation_matrix 2:W 3:b 4:fc_w 5:fc_b
//         6:Wih0 7:Whh0 8:bih0 9:bhh0 10:Wih1 11:Whh1 12:bih1 13:bhh1
// ---------------------------------------------------------------------------
extern "C" void kernel_launch(void* const* d_in, const int* in_sizes, int n_in,
                              void* d_out, int out_size)
{
    const float* x    = (const float*)d_in[0];
    const float* rel  = (const float*)d_in[1];
    const float* W    = (const float*)d_in[2];
    const float* b    = (const float*)d_in[3];
    const float* fc_w = (const float*)d_in[4];
    const float* fc_b = (const float*)d_in[5];
    const float* Wih0 = (const float*)d_in[6];
    const float* Whh0 = (const float*)d_in[7];
    const float* bih0 = (const float*)d_in[8];
    const float* bhh0 = (const float*)d_in[9];
    const float* Wih1 = (const float*)d_in[10];
    const float* Whh1 = (const float*)d_in[11];
    const float* bih1 = (const float*)d_in[12];
    const float* bhh1 = (const float*)d_in[13];
    float* out = (float*)d_out;

    const size_t gru_smem =
        (3 * GG * WPAD + GG * 8 + 4 * GG + GRU_ROWS * 360 + 2 * GRU_ROWS * 8 +
         2 * GRU_ROWS * HH + 2 * GRU_ROWS * GG) * sizeof(float);
    cudaFuncSetAttribute(gru_kernel, cudaFuncAttributeMaxDynamicSharedMemorySize,
                         (int)gru_smem);

    reldot_kernel<<<RD_BLOCKS, RD_THREADS>>>(rel, W);

    gru_kernel<<<NN / GRU_ROWS, GRU_THREADS, gru_smem>>>(
        x, Wih0, Whh0, bih0, bhh0, Wih1, Whh1, bih1, bhh1, W);

    att2_kernel<<<NN, ATT_THREADS>>>(b, fc_w, fc_b, out);
}

// round 3
// speedup vs baseline: 2.1028x; 1.2915x over previous
#include <cuda_runtime.h>
#include <math.h>
#include <stdint.h>

// Problem constants
#define NN      1024
#define DF      6
#define TT      60
#define HH      64
#define GG      192      // 3*H
#define RR      64
#define WPAD    68       // 68 floats = 272 B: every weight row start is 16B-aligned,
                         // and lane stride 3*68=204 words is conflict-free mod 32
#define NEG_VAL (-10000.0f)
#define SLOPE   0.01f

// Inter-kernel scratch (allocation-free rule: __device__ globals)
__device__ float g_h1[NN * HH];
__device__ float g_sa[NN];
__device__ float g_sb[NN];
__device__ float g_dot[NN * NN];   // 4 MB
__device__ float g_sum[NN * NN];   // 4 MB

typedef unsigned long long u64;

// Packed 2-wide fp32 FMA (Blackwell sm_100+)
__device__ __forceinline__ u64 ffma2(u64 a, u64 b, u64 c) {
    u64 d;
    asm("fma.rn.f32x2 %0, %1, %2, %3;" : "=l"(d) : "l"(a), "l"(b), "l"(c));
    return d;
}
__device__ __forceinline__ float hsum2(u64 v) {
    float lo, hi;
    asm("mov.b64 {%0,%1}, %2;" : "=f"(lo), "=f"(hi) : "l"(v));
    return lo + hi;
}
__device__ __forceinline__ float tanh_fast(float x) {
    float y;
    asm("tanh.approx.f32 %0, %1;" : "=f"(y) : "f"(x));
    return y;
}
__device__ __forceinline__ float sig_fast(float x) {
    return 0.5f * tanh_fast(0.5f * x) + 0.5f;
}

// ---------------------------------------------------------------------------
// Kernel 1: fused 2-layer GRU, persistent per-block recurrence.
// 128 blocks x 8 rows, 256 threads/block.
// Thread tile: 3 outputs x 4 rows x half-K (split-K across 2 thread groups).
// Weight rows read only 2x per step (vs 4x before) -> crossbar ~3450 cyc/step.
// ---------------------------------------------------------------------------
#define GRU_THREADS 256
#define GRU_ROWS    8

__global__ void __launch_bounds__(GRU_THREADS, 1)
gru_kernel(const float* __restrict__ x,
           const float* __restrict__ Wih0, const float* __restrict__ Whh0,
           const float* __restrict__ bih0, const float* __restrict__ bhh0,
           const float* __restrict__ Wih1, const float* __restrict__ Whh1,
           const float* __restrict__ bih1, const float* __restrict__ bhh1,
           const float* __restrict__ Wv)
{
    extern __shared__ float smem[];
    float* sWhh0 = smem;                          // 192*68
    float* sWih1 = sWhh0 + GG * WPAD;             // 192*68
    float* sWhh1 = sWih1 + GG * WPAD;             // 192*68
    float* sWih0 = sWhh1 + GG * WPAD;             // 192*8
    float* sB    = sWih0 + GG * 8;                // 4*192
    float* sX    = sB + 4 * GG;                   // 8*360
    float* sXt   = sX + GRU_ROWS * 360;           // 2*64
    float* sH0   = sXt + 2 * 64;                  // 8*64
    float* sH1   = sH0 + GRU_ROWS * HH;           // 8*64
    float* sGX0  = sH1 + GRU_ROWS * HH;           // 8*192  (layer0 x-side gates, full)
    float* sGX1p = sGX0 + GRU_ROWS * GG;          // 2*8*192 (layer1 x-side partials)
    float* sGHp  = sGX1p + 2 * GRU_ROWS * GG;     // 2*8*192 (h-side partials, reused)

    const int tid = threadIdx.x;
    const int r0  = blockIdx.x * GRU_ROWS;

    // ---- load weights / biases / x rows into SMEM ----
    for (int i = tid; i < GG * HH; i += GRU_THREADS) {
        int o = i >> 6, k = i & 63;
        sWhh0[o * WPAD + k] = Whh0[i];
        sWih1[o * WPAD + k] = Wih1[i];
        sWhh1[o * WPAD + k] = Whh1[i];
    }
    for (int i = tid; i < GG * DF; i += GRU_THREADS) {
        int o = i / DF, d = i % DF;
        sWih0[o * 8 + d] = Wih0[i];
    }
    for (int i = tid; i < GG; i += GRU_THREADS) {
        sB[i]          = bih0[i];
        sB[GG + i]     = bhh0[i];
        sB[2 * GG + i] = bih1[i];
        sB[3 * GG + i] = bhh1[i];
    }
    for (int i = tid; i < GRU_ROWS * 360; i += GRU_THREADS) {
        int r = i / 360, c = i % 360;
        sX[i] = x[(size_t)(r0 + r) * 360 + c];
    }
    for (int i = tid; i < GRU_ROWS * HH; i += GRU_THREADS) { sH0[i] = 0.f; sH1[i] = 0.f; }
    if (tid < GRU_ROWS * DF) {
        int r = tid / DF, d = tid % DF;
        sXt[r * 8 + d] = sX[r * 360 + d * TT + 0];   // xs[n][t=0][d]
    }
    __syncthreads();

    // thread tile mapping: kh (K-half) x rg (row-group) x ot (output triple)
    const int kh    = tid >> 7;        // 0..1 : K half
    const int rem   = tid & 127;
    const int rg    = rem >> 6;        // 0..1 : row group
    const int ot    = rem & 63;        // 0..63
    const int o0    = ot * 3;
    const int rbase = rg * 4;          // rows rbase..rbase+3
    const int k4b   = kh * 8;          // k4 iterations k4b..k4b+7

    for (int t = 0; t < TT; ++t) {
        const int cur = t & 1, nxt = cur ^ 1;

        // ---- Phase A: layer-0 pre-activations ----
        {
            // x-side (D=6): kh==0 threads compute full x-gates + bias
            if (kh == 0) {
                float ax[4][3];
                #pragma unroll
                for (int i = 0; i < 4; i++)
                    #pragma unroll
                    for (int j = 0; j < 3; j++) ax[i][j] = sB[o0 + j];
                #pragma unroll
                for (int d = 0; d < DF; d++) {
                    float wv0 = sWih0[(o0 + 0) * 8 + d];
                    float wv1 = sWih0[(o0 + 1) * 8 + d];
                    float wv2 = sWih0[(o0 + 2) * 8 + d];
                    #pragma unroll
                    for (int i = 0; i < 4; i++) {
                        float xv = sXt[cur * 64 + (rbase + i) * 8 + d];
                        ax[i][0] += xv * wv0; ax[i][1] += xv * wv1; ax[i][2] += xv * wv2;
                    }
                }
                #pragma unroll
                for (int i = 0; i < 4; i++)
                    #pragma unroll
                    for (int j = 0; j < 3; j++)
                        sGX0[(rbase + i) * GG + o0 + j] = ax[i][j];
            }

            // h-side: split-K partial
            u64 acc[4][3];
            #pragma unroll
            for (int i = 0; i < 4; i++)
                #pragma unroll
                for (int j = 0; j < 3; j++) acc[i][j] = 0ull;

            #pragma unroll
            for (int q = 0; q < 8; q++) {
                int k4 = k4b + q;
                ulonglong2 w0 = *(const ulonglong2*)&sWhh0[(o0 + 0) * WPAD + k4 * 4];
                ulonglong2 w1 = *(const ulonglong2*)&sWhh0[(o0 + 1) * WPAD + k4 * 4];
                ulonglong2 w2 = *(const ulonglong2*)&sWhh0[(o0 + 2) * WPAD + k4 * 4];
                #pragma unroll
                for (int i = 0; i < 4; i++) {
                    ulonglong2 hv = *(const ulonglong2*)&sH0[(rbase + i) * HH + k4 * 4];
                    acc[i][0] = ffma2(hv.x, w0.x, acc[i][0]);
                    acc[i][1] = ffma2(hv.x, w1.x, acc[i][1]);
                    acc[i][2] = ffma2(hv.x, w2.x, acc[i][2]);
                    acc[i][0] = ffma2(hv.y, w0.y, acc[i][0]);
                    acc[i][1] = ffma2(hv.y, w1.y, acc[i][1]);
                    acc[i][2] = ffma2(hv.y, w2.y, acc[i][2]);
                }
            }
            #pragma unroll
            for (int i = 0; i < 4; i++)
                #pragma unroll
                for (int j = 0; j < 3; j++)
                    sGHp[kh * GRU_ROWS * GG + (rbase + i) * GG + o0 + j] = hsum2(acc[i][j]);
        }
        __syncthreads();

        // ---- Phase B: layer-0 gates, update h0; prefetch next x_t ----
        #pragma unroll
        for (int p = 0; p < 2; p++) {
            int item = tid + p * GRU_THREADS;        // 512 items = 8 rows x 64
            int r = item >> 6, c = item & 63;
            float xr = sGX0[r * GG + c];
            float xz = sGX0[r * GG + 64 + c];
            float xn = sGX0[r * GG + 128 + c];
            float hr = sB[GG + c]       + sGHp[r * GG + c]       + sGHp[GRU_ROWS * GG + r * GG + c];
            float hz = sB[GG + 64 + c]  + sGHp[r * GG + 64 + c]  + sGHp[GRU_ROWS * GG + r * GG + 64 + c];
            float hn = sB[GG + 128 + c] + sGHp[r * GG + 128 + c] + sGHp[GRU_ROWS * GG + r * GG + 128 + c];
            float rv = sig_fast(xr + hr);
            float zv = sig_fast(xz + hz);
            float nv = tanh_fast(xn + rv * hn);
            float h  = sH0[r * HH + c];
            sH0[r * HH + c] = (1.f - zv) * nv + zv * h;
        }
        if (t + 1 < TT && tid < GRU_ROWS * DF) {
            int r = tid / DF, d = tid % DF;
            sXt[nxt * 64 + r * 8 + d] = sX[r * 360 + d * TT + (t + 1)];
        }
        __syncthreads();

        // ---- Phase C: layer-1 pre-activations (two gemms, both split-K) ----
        {
            u64 a2[4][3], b2[4][3];
            #pragma unroll
            for (int i = 0; i < 4; i++)
                #pragma unroll
                for (int j = 0; j < 3; j++) { a2[i][j] = 0ull; b2[i][j] = 0ull; }

            #pragma unroll
            for (int q = 0; q < 8; q++) {
                int k4 = k4b + q;
                ulonglong2 u0 = *(const ulonglong2*)&sWih1[(o0 + 0) * WPAD + k4 * 4];
                ulonglong2 u1 = *(const ulonglong2*)&sWih1[(o0 + 1) * WPAD + k4 * 4];
                ulonglong2 u2 = *(const ulonglong2*)&sWih1[(o0 + 2) * WPAD + k4 * 4];
                ulonglong2 w0 = *(const ulonglong2*)&sWhh1[(o0 + 0) * WPAD + k4 * 4];
                ulonglong2 w1 = *(const ulonglong2*)&sWhh1[(o0 + 1) * WPAD + k4 * 4];
                ulonglong2 w2 = *(const ulonglong2*)&sWhh1[(o0 + 2) * WPAD + k4 * 4];
                #pragma unroll
                for (int i = 0; i < 4; i++) {
                    ulonglong2 gv = *(const ulonglong2*)&sH0[(rbase + i) * HH + k4 * 4];
                    ulonglong2 vv = *(const ulonglong2*)&sH1[(rbase + i) * HH + k4 * 4];
                    a2[i][0] = ffma2(gv.x, u0.x, a2[i][0]);
                    a2[i][1] = ffma2(gv.x, u1.x, a2[i][1]);
                    a2[i][2] = ffma2(gv.x, u2.x, a2[i][2]);
                    b2[i][0] = ffma2(vv.x, w0.x, b2[i][0]);
                    b2[i][1] = ffma2(vv.x, w1.x, b2[i][1]);
                    b2[i][2] = ffma2(vv.x, w2.x, b2[i][2]);
                    a2[i][0] = ffma2(gv.y, u0.y, a2[i][0]);
                    a2[i][1] = ffma2(gv.y, u1.y, a2[i][1]);
                    a2[i][2] = ffma2(gv.y, u2.y, a2[i][2]);
                    b2[i][0] = ffma2(vv.y, w0.y, b2[i][0]);
                    b2[i][1] = ffma2(vv.y, w1.y, b2[i][1]);
                    b2[i][2] = ffma2(vv.y, w2.y, b2[i][2]);
                }
            }
            #pragma unroll
            for (int i = 0; i < 4; i++)
                #pragma unroll
                for (int j = 0; j < 3; j++) {
                    sGX1p[kh * GRU_ROWS * GG + (rbase + i) * GG + o0 + j] = hsum2(a2[i][j]);
                    sGHp [kh * GRU_ROWS * GG + (rbase + i) * GG + o0 + j] = hsum2(b2[i][j]);
                }
        }
        __syncthreads();

        // ---- Phase D: layer-1 gates, update h1 ----
        #pragma unroll
        for (int p = 0; p < 2; p++) {
            int item = tid + p * GRU_THREADS;
            int r = item >> 6, c = item & 63;
            float xr = sB[2 * GG + c]       + sGX1p[r * GG + c]       + sGX1p[GRU_ROWS * GG + r * GG + c];
            float xz = sB[2 * GG + 64 + c]  + sGX1p[r * GG + 64 + c]  + sGX1p[GRU_ROWS * GG + r * GG + 64 + c];
            float xn = sB[2 * GG + 128 + c] + sGX1p[r * GG + 128 + c] + sGX1p[GRU_ROWS * GG + r * GG + 128 + c];
            float hr = sB[3 * GG + c]       + sGHp[r * GG + c]        + sGHp[GRU_ROWS * GG + r * GG + c];
            float hz = sB[3 * GG + 64 + c]  + sGHp[r * GG + 64 + c]   + sGHp[GRU_ROWS * GG + r * GG + 64 + c];
            float hn = sB[3 * GG + 128 + c] + sGHp[r * GG + 128 + c]  + sGHp[GRU_ROWS * GG + r * GG + 128 + c];
            float rv = sig_fast(xr + hr);
            float zv = sig_fast(xz + hz);
            float nv = tanh_fast(xn + rv * hn);
            float h  = sH1[r * HH + c];
            sH1[r * HH + c] = (1.f - zv) * nv + zv * h;
        }
        __syncthreads();
    }

    // ---- epilogue: write final h1, sa = h@Wv[:H], sb = h@Wv[H:2H] ----
    for (int i = tid; i < GRU_ROWS * HH; i += GRU_THREADS)
        g_h1[(size_t)r0 * HH + i] = sH1[i];
    if (tid < GRU_ROWS) {
        float a = 0.f, b2s = 0.f;
        #pragma unroll
        for (int c = 0; c < HH; c++) {
            float h = sH1[tid * HH + c];
            a   += h * Wv[c];
            b2s += h * Wv[HH + c];
        }
        g_sa[r0 + tid] = a;
        g_sb[r0 + tid] = b2s;
    }
}

// ---------------------------------------------------------------------------
// Kernel 2: streaming rel-dot. 16 lanes per (i,j) pair, butterfly reduce.
// ---------------------------------------------------------------------------
#define RD_THREADS 256
#define RD_BLOCKS  2048

__global__ void __launch_bounds__(RD_THREADS)
reldot_kernel(const float* __restrict__ rel, const float* __restrict__ W)
{
    __shared__ float sWv[RR];
    const int tid = threadIdx.x;
    if (tid < RR) sWv[tid] = W[2 * HH + tid];
    __syncthreads();

    const int lane16 = tid & 15;
    const int grp    = tid >> 4;
    const float4 wv  = *(const float4*)&sWv[lane16 * 4];
    const int stride = RD_BLOCKS * 16;

    for (int p = blockIdx.x * 16 + grp; p < NN * NN; p += stride) {
        float4 v = *(const float4*)&rel[(size_t)p * RR + lane16 * 4];
        float dot  = v.x * wv.x + v.y * wv.y + v.z * wv.z + v.w * wv.w;
        float ssum = v.x + v.y + v.z + v.w;
        #pragma unroll
        for (int off = 8; off; off >>= 1) {
            dot  += __shfl_xor_sync(0xffffffffu, dot,  off);
            ssum += __shfl_xor_sync(0xffffffffu, ssum, off);
        }
        if (lane16 == 0) {
            g_dot[p] = dot;
            g_sum[p] = ssum;
        }
    }
}

// ---------------------------------------------------------------------------
// Kernel 3: per-row softmax + aggregation + FC. One block per node i.
// ---------------------------------------------------------------------------
#define ATT_THREADS 256

__global__ void __launch_bounds__(ATT_THREADS)
att2_kernel(const float* __restrict__ bsc,
            const float* __restrict__ fc_w,
            const float* __restrict__ fc_b,
            float* __restrict__ out)
{
    __shared__ float sTemp[NN];
    __shared__ float sMask[NN];
    __shared__ float sRed[64];
    __shared__ float sAgg[4 * HH];
    __shared__ float sBcast[2];

    const int tid = threadIdx.x;
    const int i   = blockIdx.x;

    const float sa_i = g_sa[i];
    const float bval = bsc[0];

    #pragma unroll
    for (int p = 0; p < 4; p++) {
        int j = tid + p * ATT_THREADS;
        float dot  = g_dot[(size_t)i * NN + j];
        float ssum = g_sum[(size_t)i * NN + j];
        float w = sa_i + g_sb[j] + dot + bval;
        w = (w >= 0.f) ? w : SLOPE * w;
        float m  = (ssum != 0.f) ? 1.f : 0.f;
        float tv = m * w;
        if (tv == 0.f) tv = NEG_VAL;
        sTemp[j] = tv;
        sMask[j] = m;
    }
    __syncthreads();

    float mx = -INFINITY;
    #pragma unroll
    for (int p = 0; p < 4; p++) mx = fmaxf(mx, sTemp[tid + p * ATT_THREADS]);
    #pragma unroll
    for (int off = 16; off; off >>= 1) mx = fmaxf(mx, __shfl_xor_sync(0xffffffffu, mx, off));
    if ((tid & 31) == 0) sRed[tid >> 5] = mx;
    __syncthreads();
    if (tid == 0) {
        float m2 = sRed[0];
        for (int w = 1; w < 8; w++) m2 = fmaxf(m2, sRed[w]);
        sBcast[0] = m2;
    }
    __syncthreads();
    mx = sBcast[0];

    float lsum = 0.f;
    #pragma unroll
    for (int p = 0; p < 4; p++) {
        int j = tid + p * ATT_THREADS;
        float e = __expf(sTemp[j] - mx);
        lsum += e;
        sTemp[j] = e * sMask[j];
    }
    #pragma unroll
    for (int off = 16; off; off >>= 1) lsum += __shfl_xor_sync(0xffffffffu, lsum, off);
    if ((tid & 31) == 0) sRed[tid >> 5] = lsum;
    __syncthreads();
    if (tid == 0) {
        float s2 = 0.f;
        for (int w = 0; w < 8; w++) s2 += sRed[w];
        sBcast[1] = s2;
    }
    __syncthreads();
    const float inv = 1.0f / sBcast[1];

    const int c = tid & 63, grpq = tid >> 6;
    float acc = 0.f;
    #pragma unroll 4
    for (int j = grpq; j < NN; j += 4)
        acc += sTemp[j] * g_h1[(size_t)j * HH + c];
    sAgg[grpq * HH + c] = acc;
    __syncthreads();

    if (tid < HH) {
        float agg = (sAgg[tid] + sAgg[HH + tid] + sAgg[2 * HH + tid] + sAgg[3 * HH + tid]) * inv;
        sRed[tid] = g_h1[(size_t)i * HH + tid] * fc_w[tid] + agg * fc_w[HH + tid];
    }
    __syncthreads();
    if (tid == 0) {
        float s = 0.f;
        for (int q = 0; q < HH; q++) s += sRed[q];
        out[i] = s + fc_b[0];
    }
}

// ---------------------------------------------------------------------------
// Launch
// ---------------------------------------------------------------------------
extern "C" void kernel_launch(void* const* d_in, const int* in_sizes, int n_in,
                              void* d_out, int out_size)
{
    const float* x    = (const float*)d_in[0];
    const float* rel  = (const float*)d_in[1];
    const float* W    = (const float*)d_in[2];
    const float* b    = (const float*)d_in[3];
    const float* fc_w = (const float*)d_in[4];
    const float* fc_b = (const float*)d_in[5];
    const float* Wih0 = (const float*)d_in[6];
    const float* Whh0 = (const float*)d_in[7];
    const float* bih0 = (const float*)d_in[8];
    const float* bhh0 = (const float*)d_in[9];
    const float* Wih1 = (const float*)d_in[10];
    const float* Whh1 = (const float*)d_in[11];
    const float* bih1 = (const float*)d_in[12];
    const float* bhh1 = (const float*)d_in[13];
    float* out = (float*)d_out;

    const size_t gru_smem =
        (3 * GG * WPAD + GG * 8 + 4 * GG + GRU_ROWS * 360 + 2 * 64 +
         2 * GRU_ROWS * HH + GRU_ROWS * GG + 4 * GRU_ROWS * GG) * sizeof(float);
    cudaFuncSetAttribute(gru_kernel, cudaFuncAttributeMaxDynamicSharedMemorySize,
                         (int)gru_smem);

    reldot_kernel<<<RD_BLOCKS, RD_THREADS>>>(rel, W);

    gru_kernel<<<NN / GRU_ROWS, GRU_THREADS, gru_smem>>>(
        x, Wih0, Whh0, bih0, bhh0, Wih1, Whh1, bih1, bhh1, W);

    att2_kernel<<<NN, ATT_THREADS>>>(b, fc_w, fc_b, out);
}